// round 1
// baseline (speedup 1.0000x reference)
#include <cuda_runtime.h>

#define HH 50
#define WW 50
#define NCTA 888          // 6 CTAs/SM * 148 SMs, single wave
#define TPB  64
#define BATCH 48
#define GXPAD 54          // 9 col-groups * 6
#define GYPAD 56          // 7 row-groups * 8

__device__ float g_part[NCTA][HH * WW];
__device__ float g_image[HH * WW];
__device__ float g_rowmax[HH];

__device__ __forceinline__ float fast_exp2(float x) {
    float r; asm("ex2.approx.ftz.f32 %0, %1;" : "=f"(r) : "f"(x)); return r;
}
__device__ __forceinline__ unsigned long long dup2(float f) {
    unsigned long long r; asm("mov.b64 %0, {%1, %1};" : "=l"(r) : "f"(f)); return r;
}
__device__ __forceinline__ void ffma2(unsigned long long& d, unsigned long long a, unsigned long long b) {
    asm("fma.rn.f32x2 %0, %1, %2, %0;" : "+l"(d) : "l"(a), "l"(b));
}

// Main: each CTA processes a contiguous range of points. Per batch of 48 points:
//   phase A: cooperatively stage gx[n][0..53] and w*gy[n][0..55] into SMEM (MUFU)
//   phase B: 63 active threads each own an 8-row x 6-col output tile, accumulate
//            with packed fma.rn.f32x2 (rows packed pairwise, gx duplicated).
__global__ void __launch_bounds__(TPB, 6) pi_main(
    const float2* __restrict__ pairs,
    const float*  __restrict__ sigp,
    const float*  __restrict__ gridx,
    const float*  __restrict__ gridy,
    int npts, int ppc)
{
    __shared__ float s_gx[BATCH][GXPAD];
    __shared__ float s_gy[BATCH][GYPAD];
    __shared__ float s_x[BATCH], s_y[BATCH], s_w[BATCH];
    __shared__ float s_grx[GXPAD], s_gry[GYPAD];

    const int tid = threadIdx.x;
    const float sig = *sigp;
    const float inv2s2 = 1.0f / (2.0f * sig * sig);
    const float c2 = -inv2s2 * 1.4426950408889634f;   // fold log2(e) into exponent

    if (tid < GXPAD) s_grx[tid] = (tid < WW) ? gridx[tid] : 0.0f;
    if (tid < GYPAD) s_gry[tid] = (tid < HH) ? gridy[tid] : 0.0f;

    const int rg = tid / 9;          // 0..6 row-group (8 rows each), tid 63 idle
    const int cg = tid % 9;          // 0..8 col-group (6 cols each)
    const int r0 = rg * 8;
    const int c0 = cg * 6;
    const bool active = (tid < 63);

    unsigned long long acc[4][6];    // [row-pair][col] packed f32x2 accumulators
    #pragma unroll
    for (int i = 0; i < 4; i++)
        #pragma unroll
        for (int j = 0; j < 6; j++) acc[i][j] = 0ull;

    const int pstart = blockIdx.x * ppc;
    const int pend   = min(pstart + ppc, npts);

    for (int base = pstart; base < pend; base += BATCH) {
        __syncthreads();   // previous phase B done before SMEM overwrite
        if (tid < BATCH) {
            int i = base + tid;
            float x = 0.0f, pers = 0.0f, wt = 0.0f;
            if (i < pend) {
                float2 p = pairs[i];
                x = p.x; pers = p.y - p.x; wt = pers;
            }
            s_x[tid] = x; s_y[tid] = pers; s_w[tid] = wt;
        }
        __syncthreads();
        // stage gx
        for (int idx = tid; idx < BATCH * GXPAD; idx += TPB) {
            int n = idx / GXPAD, k = idx - n * GXPAD;
            float d = s_grx[k] - s_x[n];
            float v = fast_exp2(c2 * d * d);
            s_gx[n][k] = (k < WW) ? v : 0.0f;
        }
        // stage w*gy
        for (int idx = tid; idx < BATCH * GYPAD; idx += TPB) {
            int n = idx / GYPAD, k = idx - n * GYPAD;
            float d = s_gry[k] - s_y[n];
            float v = fast_exp2(c2 * d * d) * s_w[n];
            s_gy[n][k] = (k < HH) ? v : 0.0f;
        }
        __syncthreads();
        if (active) {
            #pragma unroll 2
            for (int nn = 0; nn < BATCH; nn++) {
                const ulonglong2* gp = (const ulonglong2*)&s_gy[nn][r0];  // 16B aligned
                ulonglong2 ga = gp[0], gb = gp[1];
                unsigned long long gyp0 = ga.x, gyp1 = ga.y, gyp2 = gb.x, gyp3 = gb.y;
                float2 x01 = *(const float2*)&s_gx[nn][c0];
                float2 x23 = *(const float2*)&s_gx[nn][c0 + 2];
                float2 x45 = *(const float2*)&s_gx[nn][c0 + 4];
                unsigned long long bx[6] = { dup2(x01.x), dup2(x01.y),
                                             dup2(x23.x), dup2(x23.y),
                                             dup2(x45.x), dup2(x45.y) };
                unsigned long long gyp[4] = { gyp0, gyp1, gyp2, gyp3 };
                #pragma unroll
                for (int rp = 0; rp < 4; rp++)
                    #pragma unroll
                    for (int c = 0; c < 6; c++)
                        ffma2(acc[rp][c], gyp[rp], bx[c]);
            }
        }
    }

    // deterministic epilogue: every CTA writes its full partial tile (zeros if no points)
    float* part = g_part[blockIdx.x];
    if (active) {
        #pragma unroll
        for (int rp = 0; rp < 4; rp++) {
            #pragma unroll
            for (int c = 0; c < 6; c++) {
                int cc = c0 + c;
                if (cc < WW) {
                    float lo, hi;
                    asm("mov.b64 {%0, %1}, %2;" : "=f"(lo), "=f"(hi) : "l"(acc[rp][c]));
                    int r = r0 + 2 * rp;
                    if (r     < HH) part[r * WW + cc]       = lo;
                    if (r + 1 < HH) part[(r + 1) * WW + cc] = hi;
                }
            }
        }
    }
}

// Sum partials per pixel (deterministic, fixed order) + per-row max.
__global__ void pi_sum() {
    const int h = blockIdx.x, tid = threadIdx.x;
    __shared__ float red[TPB];
    float m = -3.0e38f;
    if (tid < WW) {
        float s0 = 0.f, s1 = 0.f, s2 = 0.f, s3 = 0.f;
        const int px = h * WW + tid;
        int c = 0;
        for (; c + 3 < NCTA; c += 4) {
            s0 += g_part[c][px];     s1 += g_part[c + 1][px];
            s2 += g_part[c + 2][px]; s3 += g_part[c + 3][px];
        }
        for (; c < NCTA; c++) s0 += g_part[c][px];
        float s = (s0 + s1) + (s2 + s3);
        g_image[px] = s;
        m = s;
    }
    red[tid] = m;
    __syncthreads();
    for (int off = 32; off > 0; off >>= 1) {
        if (tid < off) red[tid] = fmaxf(red[tid], red[tid + off]);
        __syncthreads();
    }
    if (tid == 0) g_rowmax[h] = red[0];
}

// Global max + normalize.
__global__ void pi_norm(float* __restrict__ out) {
    __shared__ float s_den;
    if (threadIdx.x == 0) {
        float m = -3.0e38f;
        for (int i = 0; i < HH; i++) m = fmaxf(m, g_rowmax[i]);
        s_den = m + 1e-8f;
    }
    __syncthreads();
    const float den = s_den;
    for (int i = threadIdx.x; i < HH * WW; i += blockDim.x)
        out[i] = g_image[i] / den;
}

extern "C" void kernel_launch(void* const* d_in, const int* in_sizes, int n_in,
                              void* d_out, int out_size) {
    const float2* pairs = (const float2*)d_in[0];
    const float*  sigma = (const float*)d_in[1];
    const float*  gx    = (const float*)d_in[2];
    const float*  gy    = (const float*)d_in[3];
    float* out = (float*)d_out;

    int npts = in_sizes[0] / 2;
    int ppc  = (npts + NCTA - 1) / NCTA;

    pi_main<<<NCTA, TPB>>>(pairs, sigma, gx, gy, npts, ppc);
    pi_sum<<<HH, TPB>>>();
    pi_norm<<<1, 256>>>(out);
}

// round 3
// speedup vs baseline: 10.1251x; 10.1251x over previous
#include <cuda_runtime.h>
#include <cstdint>

#define NB   160                 // bins per unit length
#define NBX  162                 // x bins: [0,1] + 1 pad bin each side
#define NBY  322                 // pers bins: [-1,1] + pad
#define NBINS (NBX * NBY)        // 52164
#define HCTAS 148
#define HTPB  1024
#define HH 50
#define WW 50

__device__ float g_part[HCTAS][NBINS];   // per-CTA partial histograms (~31 MB)
__device__ float g_hist[NBINS];
__device__ float g_M[HH][NBX];           // M = Gy * H
__device__ float g_image[HH * WW];
__device__ float g_rowmax[HH];

__device__ __forceinline__ float fast_exp2(float x) {
    float r; asm("ex2.approx.ftz.f32 %0, %1;" : "=f"(r) : "f"(x)); return r;
}

// ---------------- kernel 1: bilinear-splat weighted 2D histogram ----------------
// bin centers: xc(bx) = (bx - 0.5)/NB ; yc(by) = (by - 0.5)/NB - 1
// point x -> fx = x*NB + 0.5, b0 = floor(fx) in [0,160], t = frac  (x in [0,1))
// pers  p -> fy = (p+1)*NB + 0.5, b0 in [0,320]                     (p in (-1,1))
__global__ void __launch_bounds__(HTPB, 1) k_hist(
    const float2* __restrict__ pairs, int npts)
{
    extern __shared__ float hist[];
    const int tid = threadIdx.x;
    for (int i = tid; i < NBINS; i += HTPB) hist[i] = 0.0f;
    __syncthreads();

    const int stride = gridDim.x * HTPB;
    for (int i = blockIdx.x * HTPB + tid; i < npts; i += stride) {
        float2 p = pairs[i];
        float w  = p.y - p.x;                       // pers == weight
        float fx = fmaf(p.x, (float)NB, 0.5f);
        float fy = fmaf(w,   (float)NB, (float)NB + 0.5f);
        float bx0f = floorf(fx), by0f = floorf(fy);
        float tx = fx - bx0f,    ty = fy - by0f;
        int   bx0 = (int)bx0f,   by0 = (int)by0f;
        float wy1 = w * ty, wy0 = w - wy1;
        int base = by0 * NBX + bx0;
        atomicAdd(&hist[base],            wy0 * (1.0f - tx));
        atomicAdd(&hist[base + 1],        wy0 * tx);
        atomicAdd(&hist[base + NBX],      wy1 * (1.0f - tx));
        atomicAdd(&hist[base + NBX + 1],  wy1 * tx);
    }
    __syncthreads();

    float* dst = g_part[blockIdx.x];
    for (int i = tid; i < NBINS; i += HTPB) dst[i] = hist[i];
}

// ---------------- kernel 2: reduce 148 partial histograms ----------------
__global__ void k_reduce() {
    int i = blockIdx.x * blockDim.x + threadIdx.x;
    if (i >= NBINS) return;
    float s0 = 0.f, s1 = 0.f, s2 = 0.f, s3 = 0.f;
    int c = 0;
    for (; c + 3 < HCTAS; c += 4) {
        s0 += g_part[c][i];     s1 += g_part[c + 1][i];
        s2 += g_part[c + 2][i]; s3 += g_part[c + 3][i];
    }
    for (; c < HCTAS; c++) s0 += g_part[c][i];
    g_hist[i] = (s0 + s1) + (s2 + s3);
}

// ---------------- kernel 3: M[h][bx] = sum_by Gy[h][by] * H[by][bx] ----------------
__global__ void k_gemm_y(const float* __restrict__ sigp,
                         const float* __restrict__ gridy)
{
    __shared__ float gyv[NBY];
    const int h = blockIdx.x;
    const int tid = threadIdx.x;          // 352 threads
    const float sig = *sigp;
    const float c2 = -1.4426950408889634f / (2.0f * sig * sig);
    const float gh = gridy[h];

    if (tid < NBY) {
        float yc = ((float)tid - 0.5f) * (1.0f / NB) - 1.0f;
        float d = gh - yc;
        gyv[tid] = fast_exp2(c2 * d * d);
    }
    __syncthreads();

    if (tid < NBX) {
        float s0 = 0.f, s1 = 0.f;
        #pragma unroll 4
        for (int by = 0; by < NBY; by += 2) {
            s0 += gyv[by]     * g_hist[by * NBX + tid];
            s1 += gyv[by + 1] * g_hist[(by + 1) * NBX + tid];
        }
        g_M[h][tid] = s0 + s1;
    }
}

// ---------------- kernel 4: image[h][w] = sum_bx M[h][bx]*Gx[bx][w], + row max ----------------
__global__ void k_gemm_x(const float* __restrict__ sigp,
                         const float* __restrict__ gridx)
{
    __shared__ float mrow[NBX];
    __shared__ float red[2];
    const int h = blockIdx.x;
    const int tid = threadIdx.x;          // 64 threads
    const float sig = *sigp;
    const float c2 = -1.4426950408889634f / (2.0f * sig * sig);

    for (int i = tid; i < NBX; i += 64) mrow[i] = g_M[h][i];
    __syncthreads();

    float s = 0.0f;
    float m = -3.0e38f;
    if (tid < WW) {
        const float gw = gridx[tid];
        #pragma unroll 4
        for (int bx = 0; bx < NBX; bx++) {
            float xc = ((float)bx - 0.5f) * (1.0f / NB);
            float d = gw - xc;
            s += mrow[bx] * fast_exp2(c2 * d * d);
        }
        g_image[h * WW + tid] = s;
        m = s;
    }
    #pragma unroll
    for (int off = 16; off > 0; off >>= 1)
        m = fmaxf(m, __shfl_xor_sync(0xFFFFFFFFu, m, off));
    if ((tid & 31) == 0) red[tid >> 5] = m;
    __syncthreads();
    if (tid == 0) g_rowmax[h] = fmaxf(red[0], red[1]);
}

// ---------------- kernel 5: global max + normalize ----------------
__global__ void k_norm(float* __restrict__ out) {
    __shared__ float s_den;
    const int tid = threadIdx.x;          // 256 threads
    if (tid == 0) {
        float m = -3.0e38f;
        #pragma unroll
        for (int i = 0; i < HH; i++) m = fmaxf(m, g_rowmax[i]);
        s_den = m + 1e-8f;
    }
    __syncthreads();
    const float den = s_den;
    for (int i = tid; i < HH * WW; i += 256) out[i] = g_image[i] / den;
}

extern "C" void kernel_launch(void* const* d_in, const int* in_sizes, int n_in,
                              void* d_out, int out_size) {
    const float2* pairs = (const float2*)d_in[0];
    const float*  sigma = (const float*)d_in[1];
    const float*  gx    = (const float*)d_in[2];
    const float*  gy    = (const float*)d_in[3];
    float* out = (float*)d_out;

    int npts = in_sizes[0] / 2;

    static int smem_set = 0;
    if (!smem_set) {
        cudaFuncSetAttribute(k_hist, cudaFuncAttributeMaxDynamicSharedMemorySize,
                             NBINS * (int)sizeof(float));
        smem_set = 1;
    }

    k_hist<<<HCTAS, HTPB, NBINS * sizeof(float)>>>(pairs, npts);
    k_reduce<<<(NBINS + 255) / 256, 256>>>();
    k_gemm_y<<<HH, 352>>>(sigma, gy);
    k_gemm_x<<<HH, 64>>>(sigma, gx);
    k_norm<<<1, 256>>>(out);
}